// round 2
// baseline (speedup 1.0000x reference)
#include <cuda_runtime.h>
#include <cstdint>

#define N_NODES 50000
#define N_EDGES 800000
#define CDIM 128
#define NC (N_NODES * CDIM)

typedef unsigned long long u64;

// ---------------- scratch (static device globals; no allocation) ----------------
__device__ int    g_cnt[N_NODES];
__device__ int    g_off[N_NODES + 1];
__device__ int    g_cur[N_NODES];
__device__ float4 g_edge[N_EDGES];   // {lr, li, col-as-float-bits, pad}

// ---------------- packed f32x2 helpers ----------------
__device__ __forceinline__ u64 pk(float lo, float hi) {
    u64 r; asm("mov.b64 %0, {%1,%2};" : "=l"(r) : "f"(lo), "f"(hi)); return r;
}
__device__ __forceinline__ void upk(u64 v, float& lo, float& hi) {
    asm("mov.b64 {%0,%1}, %2;" : "=f"(lo), "=f"(hi) : "l"(v));
}
__device__ __forceinline__ u64 ffma2(u64 a, u64 b, u64 c) {
    u64 d; asm("fma.rn.f32x2 %0, %1, %2, %3;" : "=l"(d) : "l"(a), "l"(b), "l"(c)); return d;
}

// ---------------- counting sort pipeline ----------------
__global__ void zero_cnt_kernel() {
    int i = blockIdx.x * blockDim.x + threadIdx.x;
    if (i < N_NODES) g_cnt[i] = 0;
}

__global__ void hist_kernel(const int* __restrict__ row) {
    int e = blockIdx.x * blockDim.x + threadIdx.x;
    if (e < N_EDGES) atomicAdd(&g_cnt[row[e]], 1);
}

// single-block exclusive scan of 50000 counters
__global__ void scan_kernel() {
    __shared__ int sm[1024];
    const int CH = (N_NODES + 1023) / 1024;  // 49
    int t = threadIdx.x;
    int base = t * CH;
    int s = 0;
    for (int i = 0; i < CH; i++) {
        int idx = base + i;
        if (idx < N_NODES) s += g_cnt[idx];
    }
    sm[t] = s;
    __syncthreads();
    for (int off = 1; off < 1024; off <<= 1) {
        int v = (t >= off) ? sm[t - off] : 0;
        __syncthreads();
        sm[t] += v;
        __syncthreads();
    }
    int run = sm[t] - s;  // exclusive prefix
    for (int i = 0; i < CH; i++) {
        int idx = base + i;
        if (idx < N_NODES) {
            int v = g_cnt[idx];
            g_off[idx] = run;
            g_cur[idx] = run;
            run += v;
        }
    }
    if (t == 1023) g_off[N_NODES] = run;  // == N_EDGES
}

__global__ void scatter_kernel(const int* __restrict__ row, const int* __restrict__ col,
                               const float* __restrict__ lr, const float* __restrict__ li) {
    int e = blockIdx.x * blockDim.x + threadIdx.x;
    if (e < N_EDGES) {
        int r = row[e];
        int p = atomicAdd(&g_cur[r], 1);
        g_edge[p] = make_float4(lr[e], li[e], __int_as_float(col[e]), 0.0f);
    }
}

// ---------------- fused SpMM + GEMV + residual ----------------
#define WARPS_PB 12
#define ROWS_PW  8
#define ROWS_PB  (WARPS_PB * ROWS_PW)  // 96
#define TPB      (WARPS_PB * 32)       // 384
#define SMEM_W_BYTES   (CDIM * CDIM * 4)                 // 65536
#define SMEM_AGG_BYTES (WARPS_PB * ROWS_PW * CDIM * 8)   // 98304
#define SMEM_TOTAL     (SMEM_W_BYTES + SMEM_AGG_BYTES)   // 163840

__global__ __launch_bounds__(TPB, 1)
void fused_kernel(const float* __restrict__ Xr, const float* __restrict__ Xi,
                  const float* __restrict__ W, float* __restrict__ out) {
    extern __shared__ char smem[];
    float* Wsm  = (float*)smem;
    u64*   aggsm = (u64*)(smem + SMEM_W_BYTES);

    int tid = threadIdx.x;

    // stage W [128][128] row-major into smem
    {
        const float4* src = (const float4*)W;
        float4* dst = (float4*)Wsm;
        for (int i = tid; i < CDIM * CDIM / 4; i += TPB) dst[i] = src[i];
    }
    __syncthreads();

    int warp = tid >> 5;
    int lane = tid & 31;
    int rowBase = blockIdx.x * ROWS_PB + warp * ROWS_PW;
    u64* myAgg = aggsm + warp * ROWS_PW * CDIM;

    // ---- SpMM phase: each warp accumulates 8 rows, lane owns channels 4l..4l+3 ----
    for (int rr = 0; rr < ROWS_PW; rr++) {
        int row = rowBase + rr;
        u64 ar01 = 0, ar23 = 0, ai01 = 0, ai23 = 0;  // channel-paired accumulators
        if (row < N_NODES) {
            int e   = g_off[row];
            int end = g_off[row + 1];
            if (e < end) {
                // 2-stage software pipeline: prefetch next edge while computing current
                float4 md = __ldg(&g_edge[e]);
                int c = __float_as_int(md.z);
                ulonglong2 xr = *(const ulonglong2*)(Xr + c * CDIM + 4 * lane);
                ulonglong2 xi = *(const ulonglong2*)(Xi + c * CDIM + 4 * lane);
                while (e < end) {
                    int en = e + 1;
                    float4 mdn = make_float4(0.f, 0.f, 0.f, 0.f);
                    ulonglong2 xrn = xr, xin = xi;
                    if (en < end) {
                        mdn = __ldg(&g_edge[en]);
                        int cn = __float_as_int(mdn.z);
                        xrn = *(const ulonglong2*)(Xr + cn * CDIM + 4 * lane);
                        xin = *(const ulonglong2*)(Xi + cn * CDIM + 4 * lane);
                    }
                    u64 lrd  = pk(md.x,  md.x);
                    u64 lid  = pk(md.y,  md.y);
                    u64 nlid = pk(-md.y, -md.y);
                    // agg_real += lr*xr - li*xi ; agg_imag += li*xr + lr*xi
                    ar01 = ffma2(lrd,  xr.x, ar01);
                    ar23 = ffma2(lrd,  xr.y, ar23);
                    ai01 = ffma2(lid,  xr.x, ai01);
                    ai23 = ffma2(lid,  xr.y, ai23);
                    ar01 = ffma2(nlid, xi.x, ar01);
                    ar23 = ffma2(nlid, xi.y, ar23);
                    ai01 = ffma2(lrd,  xi.x, ai01);
                    ai23 = ffma2(lrd,  xi.y, ai23);
                    md = mdn; xr = xrn; xi = xin;
                    e = en;
                }
            }
        }
        // store interleaved {ar_k, ai_k} pairs for GEMV broadcast
        float a0, a1, a2, a3, b0, b1, b2, b3;
        upk(ar01, a0, a1); upk(ar23, a2, a3);
        upk(ai01, b0, b1); upk(ai23, b2, b3);
        u64* dst = myAgg + rr * CDIM + 4 * lane;
        dst[0] = pk(a0, b0); dst[1] = pk(a1, b1);
        dst[2] = pk(a2, b2); dst[3] = pk(a3, b3);
    }
    __syncwarp();

    // ---- GEMV phase: 8-row blocked, lane owns output cols j=4l..4l+3 ----
    u64 acc[ROWS_PW][4];
    #pragma unroll
    for (int rr = 0; rr < ROWS_PW; rr++) {
        int row = rowBase + rr;
        if (row < N_NODES) {
            // init with residual X
            float4 xr4 = *(const float4*)(Xr + row * CDIM + 4 * lane);
            float4 xi4 = *(const float4*)(Xi + row * CDIM + 4 * lane);
            acc[rr][0] = pk(xr4.x, xr4.y); acc[rr][1] = pk(xr4.z, xr4.w);
            acc[rr][2] = pk(xi4.x, xi4.y); acc[rr][3] = pk(xi4.z, xi4.w);
        } else {
            acc[rr][0] = acc[rr][1] = acc[rr][2] = acc[rr][3] = 0ull;
        }
    }

    const ulonglong2* Wv = (const ulonglong2*)Wsm;  // k*32 + lane -> W[k][4l..4l+3]
    #pragma unroll 4
    for (int k = 0; k < CDIM; k++) {
        ulonglong2 w = Wv[k * 32 + lane];
        #pragma unroll
        for (int rr = 0; rr < ROWS_PW; rr++) {
            u64 a = myAgg[rr * CDIM + k];      // broadcast LDS.64
            float arf, aif; upk(a, arf, aif);
            u64 dr = pk(arf, arf);
            u64 di = pk(aif, aif);
            acc[rr][0] = ffma2(w.x, dr, acc[rr][0]);
            acc[rr][1] = ffma2(w.y, dr, acc[rr][1]);
            acc[rr][2] = ffma2(w.x, di, acc[rr][2]);
            acc[rr][3] = ffma2(w.y, di, acc[rr][3]);
        }
    }

    float* outR = out;
    float* outI = out + NC;
    #pragma unroll
    for (int rr = 0; rr < ROWS_PW; rr++) {
        int row = rowBase + rr;
        if (row < N_NODES) {
            float4 r4, i4;
            upk(acc[rr][0], r4.x, r4.y); upk(acc[rr][1], r4.z, r4.w);
            upk(acc[rr][2], i4.x, i4.y); upk(acc[rr][3], i4.z, i4.w);
            *(float4*)(outR + row * CDIM + 4 * lane) = r4;
            *(float4*)(outI + row * CDIM + 4 * lane) = i4;
        }
    }
}

// ---------------- launch ----------------
extern "C" void kernel_launch(void* const* d_in, const int* in_sizes, int n_in,
                              void* d_out, int out_size) {
    const float* Xr = (const float*)d_in[0];
    const float* Xi = (const float*)d_in[1];
    const float* Lr = (const float*)d_in[2];
    const float* Li = (const float*)d_in[3];
    const float* W  = (const float*)d_in[4];
    const int*   row = (const int*)d_in[5];
    const int*   col = (const int*)d_in[6];
    float* out = (float*)d_out;

    zero_cnt_kernel<<<(N_NODES + 255) / 256, 256>>>();
    hist_kernel<<<(N_EDGES + 255) / 256, 256>>>(row);
    scan_kernel<<<1, 1024>>>();
    scatter_kernel<<<(N_EDGES + 255) / 256, 256>>>(row, col, Lr, Li);

    cudaFuncSetAttribute(fused_kernel, cudaFuncAttributeMaxDynamicSharedMemorySize, SMEM_TOTAL);
    int blocks = (N_NODES + ROWS_PB - 1) / ROWS_PB;
    fused_kernel<<<blocks, TPB, SMEM_TOTAL>>>(Xr, Xi, W, out);
}

// round 3
// speedup vs baseline: 1.2127x; 1.2127x over previous
#include <cuda_runtime.h>
#include <cstdint>

#define N_NODES 50000
#define N_EDGES 800000
#define CDIM 128
#define NC (N_NODES * CDIM)

typedef unsigned long long u64;

// ---------------- scratch (static device globals; no allocation) ----------------
__device__ int    g_cnt[N_NODES];
__device__ int    g_off[N_NODES + 1];
__device__ int    g_cur[N_NODES];
__device__ int    g_colx[N_EDGES];
__device__ float2 g_valx[N_EDGES];

// ---------------- packed f32x2 helpers ----------------
__device__ __forceinline__ u64 pk(float lo, float hi) {
    u64 r; asm("mov.b64 %0, {%1,%2};" : "=l"(r) : "f"(lo), "f"(hi)); return r;
}
__device__ __forceinline__ void upk(u64 v, float& lo, float& hi) {
    asm("mov.b64 {%0,%1}, %2;" : "=f"(lo), "=f"(hi) : "l"(v));
}
__device__ __forceinline__ u64 ffma2(u64 a, u64 b, u64 c) {
    u64 d; asm("fma.rn.f32x2 %0, %1, %2, %3;" : "=l"(d) : "l"(a), "l"(b), "l"(c)); return d;
}

// ---------------- counting sort pipeline ----------------
__global__ void zero_cnt_kernel() {
    int i = blockIdx.x * blockDim.x + threadIdx.x;
    if (i < N_NODES) g_cnt[i] = 0;
}

__global__ void hist_kernel(const int* __restrict__ row) {
    int e = blockIdx.x * blockDim.x + threadIdx.x;
    if (e < N_EDGES) atomicAdd(&g_cnt[row[e]], 1);
}

// single-block exclusive scan of 50000 counters
__global__ void scan_kernel() {
    __shared__ int sm[1024];
    const int CH = (N_NODES + 1023) / 1024;  // 49
    int t = threadIdx.x;
    int base = t * CH;
    int s = 0;
    for (int i = 0; i < CH; i++) {
        int idx = base + i;
        if (idx < N_NODES) s += g_cnt[idx];
    }
    sm[t] = s;
    __syncthreads();
    for (int off = 1; off < 1024; off <<= 1) {
        int v = (t >= off) ? sm[t - off] : 0;
        __syncthreads();
        sm[t] += v;
        __syncthreads();
    }
    int run = sm[t] - s;  // exclusive prefix
    for (int i = 0; i < CH; i++) {
        int idx = base + i;
        if (idx < N_NODES) {
            int v = g_cnt[idx];
            g_off[idx] = run;
            g_cur[idx] = run;
            run += v;
        }
    }
    if (t == 1023) g_off[N_NODES] = run;  // == N_EDGES
}

__global__ void scatter_kernel(const int* __restrict__ row, const int* __restrict__ col,
                               const float* __restrict__ lr, const float* __restrict__ li) {
    int e = blockIdx.x * blockDim.x + threadIdx.x;
    if (e < N_EDGES) {
        int r = row[e];
        int p = atomicAdd(&g_cur[r], 1);
        g_colx[p] = col[e];
        g_valx[p] = make_float2(lr[e], li[e]);
    }
}

// ---------------- fused SpMM + GEMV + residual ----------------
#define WARPS_PB 10
#define TPB      (WARPS_PB * 32)       // 320
#define RPP      4                     // rows per pass (per warp)
#define PASSES   2
#define ROWS_PW  (RPP * PASSES)        // 8
#define ROWS_PB  (WARPS_PB * ROWS_PW)  // 80
#define SMEM_W_BYTES   (CDIM * CDIM * 4)           // 65536
#define SMEM_AGG_BYTES (WARPS_PB * RPP * CDIM * 8) // 40960
#define SMEM_TOTAL     (SMEM_W_BYTES + SMEM_AGG_BYTES)  // 106496 -> 2 blocks/SM

// one edge's complex FMA on one register slot + prefetch of slot's next edge
#define SLOT_BODY(XR, XI, J) do {                                              \
    float vr = __shfl_sync(0xffffffffu, mv.x, (J));                            \
    float vi = __shfl_sync(0xffffffffu, mv.y, (J));                            \
    u64 vr2 = pk(vr, vr), vi2 = pk(vi, vi), nvi2 = pk(-vi, -vi);               \
    ar01 = ffma2(vr2,  XR.x, ar01); ar23 = ffma2(vr2,  XR.y, ar23);            \
    ai01 = ffma2(vi2,  XR.x, ai01); ai23 = ffma2(vi2,  XR.y, ai23);            \
    ar01 = ffma2(nvi2, XI.x, ar01); ar23 = ffma2(nvi2, XI.y, ar23);            \
    ai01 = ffma2(vr2,  XI.x, ai01); ai23 = ffma2(vr2,  XI.y, ai23);            \
    int jn = (J) + 4;                                                          \
    if (jn < cnt) {                                                            \
        int cn = __shfl_sync(0xffffffffu, mc, jn);                             \
        XR = *(const ulonglong2*)(XrL + (cn << 7));                            \
        XI = *(const ulonglong2*)(XiL + (cn << 7));                            \
    }                                                                          \
} while (0)

__global__ __launch_bounds__(TPB, 2)
void fused_kernel(const float* __restrict__ Xr, const float* __restrict__ Xi,
                  const float* __restrict__ W, float* __restrict__ out) {
    extern __shared__ char smem[];
    float* Wsm   = (float*)smem;
    u64*   aggsm = (u64*)(smem + SMEM_W_BYTES);

    int tid = threadIdx.x;

    // stage W [128][128] row-major into smem
    {
        const float4* src = (const float4*)W;
        float4* dst = (float4*)Wsm;
        for (int i = tid; i < CDIM * CDIM / 4; i += TPB) dst[i] = src[i];
    }
    __syncthreads();

    int warp = tid >> 5;
    int lane = tid & 31;
    u64* myAgg = aggsm + warp * RPP * CDIM;
    const ulonglong2* Wv = (const ulonglong2*)Wsm;  // k*32 + lane -> W[k][4l..4l+3]
    const float* XrL = Xr + 4 * lane;
    const float* XiL = Xi + 4 * lane;
    float* outR = out;
    float* outI = out + NC;

    for (int pass = 0; pass < PASSES; pass++) {
        int rowBase = blockIdx.x * ROWS_PB + warp * ROWS_PW + pass * RPP;

        // ---- SpMM phase: warp-cooperative metadata, depth-4 pipelined gather ----
        for (int rr = 0; rr < RPP; rr++) {
            int row = rowBase + rr;
            u64 ar01 = 0, ar23 = 0, ai01 = 0, ai23 = 0;
            if (row < N_NODES) {
                int e0  = g_off[row];
                int deg = g_off[row + 1] - e0;
                for (int base = 0; base < deg; base += 32) {
                    int cnt = min(32, deg - base);
                    int mc = 0; float2 mv = make_float2(0.f, 0.f);
                    if (lane < cnt) {
                        mc = g_colx[e0 + base + lane];
                        mv = g_valx[e0 + base + lane];
                    }
                    ulonglong2 xr0, xi0, xr1, xi1, xr2, xi2, xr3, xi3;
                    // prologue: all gather addresses known via shfl; issue 4 deep
                    {
                        int c0 = __shfl_sync(0xffffffffu, mc, 0);
                        int c1 = __shfl_sync(0xffffffffu, mc, 1);
                        int c2 = __shfl_sync(0xffffffffu, mc, 2);
                        int c3 = __shfl_sync(0xffffffffu, mc, 3);
                        xr0 = *(const ulonglong2*)(XrL + (c0 << 7));
                        xi0 = *(const ulonglong2*)(XiL + (c0 << 7));
                        if (1 < cnt) { xr1 = *(const ulonglong2*)(XrL + (c1 << 7));
                                       xi1 = *(const ulonglong2*)(XiL + (c1 << 7)); }
                        if (2 < cnt) { xr2 = *(const ulonglong2*)(XrL + (c2 << 7));
                                       xi2 = *(const ulonglong2*)(XiL + (c2 << 7)); }
                        if (3 < cnt) { xr3 = *(const ulonglong2*)(XrL + (c3 << 7));
                                       xi3 = *(const ulonglong2*)(XiL + (c3 << 7)); }
                    }
                    for (int j = 0; j < cnt; j += 4) {
                        SLOT_BODY(xr0, xi0, j);
                        if (j + 1 < cnt) SLOT_BODY(xr1, xi1, j + 1);
                        if (j + 2 < cnt) SLOT_BODY(xr2, xi2, j + 2);
                        if (j + 3 < cnt) SLOT_BODY(xr3, xi3, j + 3);
                    }
                }
            }
            // store interleaved {ar_k, ai_k} pairs for GEMV broadcast
            float a0, a1, a2, a3, b0, b1, b2, b3;
            upk(ar01, a0, a1); upk(ar23, a2, a3);
            upk(ai01, b0, b1); upk(ai23, b2, b3);
            u64* dst = myAgg + rr * CDIM + 4 * lane;
            dst[0] = pk(a0, b0); dst[1] = pk(a1, b1);
            dst[2] = pk(a2, b2); dst[3] = pk(a3, b3);
        }
        __syncwarp();

        // ---- GEMV phase: 4-row blocked, lane owns output cols j=4l..4l+3 ----
        u64 acc[RPP][4];
        #pragma unroll
        for (int rr = 0; rr < RPP; rr++) {
            int row = rowBase + rr;
            if (row < N_NODES) {
                float4 xr4 = *(const float4*)(Xr + row * CDIM + 4 * lane);
                float4 xi4 = *(const float4*)(Xi + row * CDIM + 4 * lane);
                acc[rr][0] = pk(xr4.x, xr4.y); acc[rr][1] = pk(xr4.z, xr4.w);
                acc[rr][2] = pk(xi4.x, xi4.y); acc[rr][3] = pk(xi4.z, xi4.w);
            } else {
                acc[rr][0] = acc[rr][1] = acc[rr][2] = acc[rr][3] = 0ull;
            }
        }

        #pragma unroll 4
        for (int k = 0; k < CDIM; k++) {
            ulonglong2 w = Wv[k * 32 + lane];
            #pragma unroll
            for (int rr = 0; rr < RPP; rr++) {
                u64 a = myAgg[rr * CDIM + k];   // broadcast LDS.64
                float arf, aif; upk(a, arf, aif);
                u64 dr = pk(arf, arf);
                u64 di = pk(aif, aif);
                acc[rr][0] = ffma2(w.x, dr, acc[rr][0]);
                acc[rr][1] = ffma2(w.y, dr, acc[rr][1]);
                acc[rr][2] = ffma2(w.x, di, acc[rr][2]);
                acc[rr][3] = ffma2(w.y, di, acc[rr][3]);
            }
        }

        #pragma unroll
        for (int rr = 0; rr < RPP; rr++) {
            int row = rowBase + rr;
            if (row < N_NODES) {
                float4 r4, i4;
                upk(acc[rr][0], r4.x, r4.y); upk(acc[rr][1], r4.z, r4.w);
                upk(acc[rr][2], i4.x, i4.y); upk(acc[rr][3], i4.z, i4.w);
                *(float4*)(outR + row * CDIM + 4 * lane) = r4;
                *(float4*)(outI + row * CDIM + 4 * lane) = i4;
            }
        }
        __syncwarp();  // protect myAgg before next pass overwrites it
    }
}

// ---------------- launch ----------------
extern "C" void kernel_launch(void* const* d_in, const int* in_sizes, int n_in,
                              void* d_out, int out_size) {
    const float* Xr = (const float*)d_in[0];
    const float* Xi = (const float*)d_in[1];
    const float* Lr = (const float*)d_in[2];
    const float* Li = (const float*)d_in[3];
    const float* W  = (const float*)d_in[4];
    const int*   row = (const int*)d_in[5];
    const int*   col = (const int*)d_in[6];
    float* out = (float*)d_out;

    zero_cnt_kernel<<<(N_NODES + 255) / 256, 256>>>();
    hist_kernel<<<(N_EDGES + 255) / 256, 256>>>(row);
    scan_kernel<<<1, 1024>>>();
    scatter_kernel<<<(N_EDGES + 255) / 256, 256>>>(row, col, Lr, Li);

    cudaFuncSetAttribute(fused_kernel, cudaFuncAttributeMaxDynamicSharedMemorySize, SMEM_TOTAL);
    int blocks = (N_NODES + ROWS_PB - 1) / ROWS_PB;
    fused_kernel<<<blocks, TPB, SMEM_TOTAL>>>(Xr, Xi, W, out);
}